// round 1
// baseline (speedup 1.0000x reference)
#include <cuda_runtime.h>

// ---------------- scratch (device globals; no allocation allowed) ----------
#define NMAX 131072
__device__ float    g_u1[NMAX * 64];
__device__ float    g_v1[NMAX * 64];
__device__ float    g_h1[NMAX * 64];
__device__ unsigned g_M1[NMAX * 64];
__device__ float    g_u2[NMAX * 128];
__device__ float    g_v2[NMAX * 128];
__device__ unsigned g_M2[NMAX * 128];

// Monotone order-preserving float <-> u32 key (for atomicMax on floats of any sign)
__device__ __forceinline__ unsigned f2k(float f) {
    unsigned u = __float_as_uint(f);
    return (u & 0x80000000u) ? ~u : (u | 0x80000000u);
}
__device__ __forceinline__ float k2f(unsigned k) {
    return (k & 0x80000000u) ? __uint_as_float(k & 0x7FFFFFFFu)
                             : __uint_as_float(~k);
}
// f2k(-inf) = ~0xFF800000 = 0x007FFFFF
#define INIT_KEY 0x007FFFFFu

// ---------------- kernels --------------------------------------------------

__global__ void k_init(int n) {
    int i = blockIdx.x * blockDim.x + threadIdx.x;
    int t1 = n * 64;
    if (i < t1) { g_M1[i] = INIT_KEY; return; }
    int j = i - t1;
    if (j < n * 128) g_M2[j] = INIT_KEY;
}

// layer 1 per-node: u1 = x@(W1a+W1b)+b1, v1 = x@W1b   (W1: [6,64] row-major)
__global__ void k_u1v1(const float* __restrict__ x, const float* __restrict__ W1,
                       const float* __restrict__ b1, int n) {
    int i = blockIdx.x * blockDim.x + threadIdx.x;
    if (i >= n * 64) return;
    int node = i >> 6, c = i & 63;
    float x0 = x[node * 3 + 0], x1 = x[node * 3 + 1], x2 = x[node * 3 + 2];
    float wa0 = W1[0 * 64 + c], wa1 = W1[1 * 64 + c], wa2 = W1[2 * 64 + c];
    float wb0 = W1[3 * 64 + c], wb1 = W1[4 * 64 + c], wb2 = W1[5 * 64 + c];
    float v = x0 * wb0 + x1 * wb1 + x2 * wb2;
    float u = x0 * (wa0 + wb0) + x1 * (wa1 + wb1) + x2 * (wa2 + wb2) + b1[c];
    g_u1[i] = u;
    g_v1[i] = v;
}

// edge scatter-max into M1 (64 comps/edge); pre-filter load before atomic
__global__ void k_edge1(const int* __restrict__ src, const int* __restrict__ dst,
                        int total) {
    int i = blockIdx.x * blockDim.x + threadIdx.x;
    if (i >= total) return;
    int e = i >> 6, c = i & 63;
    int s = __ldg(src + e), d = __ldg(dst + e);
    unsigned key = f2k(g_u1[s * 64 + c]);
    unsigned* addr = &g_M1[d * 64 + c];
    if (key > *addr) atomicMax(addr, key);
}

// h1 = relu(max - v1)
__global__ void k_h1(int n) {
    int i = blockIdx.x * blockDim.x + threadIdx.x;
    if (i >= n * 64) return;
    g_h1[i] = fmaxf(k2f(g_M1[i]) - g_v1[i], 0.0f);
}

// layer 2 per-node: u2 = h1@W2[0:64] + x@W2[64:67] + b2, v2 = x@W2[64:67]
// one block (128 threads) per node
__global__ void k_u2v2(const float* __restrict__ x, const float* __restrict__ W2,
                       const float* __restrict__ b2, int n) {
    int node = blockIdx.x;
    if (node >= n) return;
    __shared__ float sh[64];
    __shared__ float sx[3];
    int c = threadIdx.x;
    if (c < 64) sh[c] = g_h1[node * 64 + c];
    if (c < 3)  sx[c] = x[node * 3 + c];
    __syncthreads();
    float acc = b2[c];
#pragma unroll 16
    for (int k = 0; k < 64; k++) acc += sh[k] * W2[k * 128 + c];
    float vv = sx[0] * W2[64 * 128 + c] + sx[1] * W2[65 * 128 + c] +
               sx[2] * W2[66 * 128 + c];
    g_u2[node * 128 + c] = acc + vv;
    g_v2[node * 128 + c] = vv;
}

// edge scatter-max into M2 (128 comps/edge)
__global__ void k_edge2(const int* __restrict__ src, const int* __restrict__ dst,
                        int total) {
    int i = blockIdx.x * blockDim.x + threadIdx.x;
    if (i >= total) return;
    int e = i >> 7, c = i & 127;
    int s = __ldg(src + e), d = __ldg(dst + e);
    unsigned key = f2k(g_u2[s * 128 + c]);
    unsigned* addr = &g_M2[d * 128 + c];
    if (key > *addr) atomicMax(addr, key);
}

// final: h2 = relu(max - v2); logits = h2@Wc + bc; log_softmax. 1 warp / node.
__global__ void k_out(const float* __restrict__ Wc, const float* __restrict__ bc,
                      float* __restrict__ out, int n) {
    int gt = blockIdx.x * blockDim.x + threadIdx.x;
    int node = gt >> 5;
    int lane = gt & 31;
    if (node >= n) return;
    float a0 = 0.f, a1 = 0.f, a2 = 0.f, a3 = 0.f, a4 = 0.f;
#pragma unroll
    for (int r = 0; r < 4; r++) {
        int c = lane + r * 32;
        float h = fmaxf(k2f(g_M2[node * 128 + c]) - g_v2[node * 128 + c], 0.0f);
        const float* w = Wc + c * 5;
        a0 += h * w[0]; a1 += h * w[1]; a2 += h * w[2]; a3 += h * w[3]; a4 += h * w[4];
    }
#pragma unroll
    for (int o = 16; o; o >>= 1) {
        a0 += __shfl_xor_sync(0xFFFFFFFFu, a0, o);
        a1 += __shfl_xor_sync(0xFFFFFFFFu, a1, o);
        a2 += __shfl_xor_sync(0xFFFFFFFFu, a2, o);
        a3 += __shfl_xor_sync(0xFFFFFFFFu, a3, o);
        a4 += __shfl_xor_sync(0xFFFFFFFFu, a4, o);
    }
    if (lane == 0) {
        float l0 = a0 + bc[0], l1 = a1 + bc[1], l2 = a2 + bc[2];
        float l3 = a3 + bc[3], l4 = a4 + bc[4];
        float m = fmaxf(fmaxf(fmaxf(l0, l1), fmaxf(l2, l3)), l4);
        float s = expf(l0 - m) + expf(l1 - m) + expf(l2 - m) +
                  expf(l3 - m) + expf(l4 - m);
        float lse = m + logf(s);
        float* o = out + node * 5;
        o[0] = l0 - lse; o[1] = l1 - lse; o[2] = l2 - lse;
        o[3] = l3 - lse; o[4] = l4 - lse;
    }
}

// ---------------- launch ----------------------------------------------------
extern "C" void kernel_launch(void* const* d_in, const int* in_sizes, int n_in,
                              void* d_out, int out_size) {
    const float* x  = (const float*)d_in[0];
    const int*   ei = (const int*)d_in[1];
    const float* W1 = (const float*)d_in[2];
    const float* b1 = (const float*)d_in[3];
    const float* W2 = (const float*)d_in[4];
    const float* b2 = (const float*)d_in[5];
    const float* Wc = (const float*)d_in[6];
    const float* bc = (const float*)d_in[7];
    float* out = (float*)d_out;

    int n = in_sizes[0] / 3;       // 100000
    int e = in_sizes[1] / 2;       // 1600000
    const int* src = ei;
    const int* dst = ei + e;

    const int T = 256;
    k_init <<<(n * 192 + T - 1) / T, T>>>(n);
    k_u1v1 <<<(n * 64 + T - 1) / T, T>>>(x, W1, b1, n);
    k_edge1<<<(e * 64 + T - 1) / T, T>>>(src, dst, e * 64);
    k_h1   <<<(n * 64 + T - 1) / T, T>>>(n);
    k_u2v2 <<<n, 128>>>(x, W2, b2, n);
    k_edge2<<<((long long)e * 128 + T - 1) / T, T>>>(src, dst, e * 128);
    k_out  <<<((long long)n * 32 + T - 1) / T, T>>>(Wc, bc, out, n);
}

// round 2
// speedup vs baseline: 2.7427x; 2.7427x over previous
#include <cuda_runtime.h>
#include <math_constants.h>

// ---------------- scratch (device globals; no allocation allowed) ----------
#define NMAX 131072
#define EMAX 2097152

__device__ float g_u1[NMAX * 64];
__device__ float g_v1[NMAX * 64];
__device__ float g_h1[NMAX * 64];
__device__ float g_u2[NMAX * 128];
__device__ float g_v2[NMAX * 128];
__device__ int   g_cnt[NMAX];
__device__ int   g_off[NMAX + 1];
__device__ int   g_cur[NMAX];
__device__ int   g_part[1024];
__device__ int   g_srcs[EMAX];

// ---------------- node precompute -------------------------------------------

// layer 1 per-node: u1 = x@(W1a+W1b)+b1, v1 = x@W1b   (W1: [6,64] row-major)
// also zeroes g_cnt (one thread per node does it)
__global__ void k_u1v1(const float* __restrict__ x, const float* __restrict__ W1,
                       const float* __restrict__ b1, int n) {
    int i = blockIdx.x * blockDim.x + threadIdx.x;
    if (i >= n * 64) return;
    int node = i >> 6, c = i & 63;
    if (c == 0) g_cnt[node] = 0;
    float x0 = x[node * 3 + 0], x1 = x[node * 3 + 1], x2 = x[node * 3 + 2];
    float wa0 = W1[0 * 64 + c], wa1 = W1[1 * 64 + c], wa2 = W1[2 * 64 + c];
    float wb0 = W1[3 * 64 + c], wb1 = W1[4 * 64 + c], wb2 = W1[5 * 64 + c];
    float v = x0 * wb0 + x1 * wb1 + x2 * wb2;
    float u = x0 * (wa0 + wb0) + x1 * (wa1 + wb1) + x2 * (wa2 + wb2) + b1[c];
    g_u1[i] = u;
    g_v1[i] = v;
}

// ---------------- CSR build (dst-sorted) ------------------------------------

__global__ void k_hist(const int* __restrict__ dst, int e) {
    int i = blockIdx.x * blockDim.x + threadIdx.x;
    if (i < e) atomicAdd(&g_cnt[dst[i]], 1);
}

// block-level exclusive scan (1024 per block), block totals to g_part
__global__ void k_scan_block(int n) {
    __shared__ int sh[1024];
    int i = blockIdx.x * 1024 + threadIdx.x;
    int v = (i < n) ? g_cnt[i] : 0;
    sh[threadIdx.x] = v;
    __syncthreads();
#pragma unroll
    for (int o = 1; o < 1024; o <<= 1) {
        int t = (threadIdx.x >= o) ? sh[threadIdx.x - o] : 0;
        __syncthreads();
        sh[threadIdx.x] += t;
        __syncthreads();
    }
    if (i < n) g_off[i] = sh[threadIdx.x] - v;  // block-local exclusive
    if (threadIdx.x == 1023) g_part[blockIdx.x] = sh[1023];
}

// single-block scan of block partials (nb <= 1024)
__global__ void k_scan_part(int nb) {
    __shared__ int sh[1024];
    int v = (threadIdx.x < nb) ? g_part[threadIdx.x] : 0;
    sh[threadIdx.x] = v;
    __syncthreads();
#pragma unroll
    for (int o = 1; o < 1024; o <<= 1) {
        int t = (threadIdx.x >= o) ? sh[threadIdx.x - o] : 0;
        __syncthreads();
        sh[threadIdx.x] += t;
        __syncthreads();
    }
    if (threadIdx.x < nb) g_part[threadIdx.x] = sh[threadIdx.x] - v;  // exclusive
}

__global__ void k_scan_add(int n) {
    int i = blockIdx.x * blockDim.x + threadIdx.x;
    if (i >= n) return;
    int o = g_off[i] + g_part[i >> 10];
    g_off[i] = o;
    g_cur[i] = o;
    if (i == n - 1) g_off[n] = o + g_cnt[i];
}

__global__ void k_scatter(const int* __restrict__ src, const int* __restrict__ dst,
                          int e) {
    int i = blockIdx.x * blockDim.x + threadIdx.x;
    if (i >= e) return;
    int d = dst[i];
    int p = atomicAdd(&g_cur[d], 1);
    g_srcs[p] = src[i];
}

// ---------------- aggregation ------------------------------------------------

// layer-1 gather-max + relu: one warp per node, 2 comps per lane
__global__ void k_agg1(int n) {
    int gt = blockIdx.x * blockDim.x + threadIdx.x;
    int node = gt >> 5, lane = gt & 31;
    if (node >= n) return;
    int off = g_off[node], end = g_off[node + 1];
    float mx = -CUDART_INF_F, my = -CUDART_INF_F;
    int j = off;
    for (; j + 1 < end; j += 2) {
        int s0 = g_srcs[j], s1 = g_srcs[j + 1];
        float2 a = *(const float2*)&g_u1[s0 * 64 + lane * 2];
        float2 b = *(const float2*)&g_u1[s1 * 64 + lane * 2];
        mx = fmaxf(mx, fmaxf(a.x, b.x));
        my = fmaxf(my, fmaxf(a.y, b.y));
    }
    if (j < end) {
        int s0 = g_srcs[j];
        float2 a = *(const float2*)&g_u1[s0 * 64 + lane * 2];
        mx = fmaxf(mx, a.x);
        my = fmaxf(my, a.y);
    }
    float2 v = *(const float2*)&g_v1[node * 64 + lane * 2];
    float2 h;
    h.x = fmaxf(mx - v.x, 0.0f);
    h.y = fmaxf(my - v.y, 0.0f);
    *(float2*)&g_h1[node * 64 + lane * 2] = h;
}

// layer 2 per-node: u2 = h1@W2[0:64] + x@W2[64:67] + b2, v2 = x@W2[64:67]
__global__ void k_u2v2(const float* __restrict__ x, const float* __restrict__ W2,
                       const float* __restrict__ b2, int n) {
    int node = blockIdx.x;
    if (node >= n) return;
    __shared__ float sh[64];
    __shared__ float sx[3];
    int c = threadIdx.x;
    if (c < 64) sh[c] = g_h1[node * 64 + c];
    if (c < 3)  sx[c] = x[node * 3 + c];
    __syncthreads();
    float acc = b2[c];
#pragma unroll 16
    for (int k = 0; k < 64; k++) acc += sh[k] * W2[k * 128 + c];
    float vv = sx[0] * W2[64 * 128 + c] + sx[1] * W2[65 * 128 + c] +
               sx[2] * W2[66 * 128 + c];
    g_u2[node * 128 + c] = acc + vv;
    g_v2[node * 128 + c] = vv;
}

// layer-2 gather-max fused with output head: one warp per node, 4 comps/lane
__global__ void k_agg2out(const float* __restrict__ Wc, const float* __restrict__ bc,
                          float* __restrict__ out, int n) {
    int gt = blockIdx.x * blockDim.x + threadIdx.x;
    int node = gt >> 5, lane = gt & 31;
    if (node >= n) return;
    int off = g_off[node], end = g_off[node + 1];
    float m0 = -CUDART_INF_F, m1 = m0, m2 = m0, m3 = m0;
    int j = off;
    for (; j + 1 < end; j += 2) {
        int s0 = g_srcs[j], s1 = g_srcs[j + 1];
        float4 a = *(const float4*)&g_u2[s0 * 128 + lane * 4];
        float4 b = *(const float4*)&g_u2[s1 * 128 + lane * 4];
        m0 = fmaxf(m0, fmaxf(a.x, b.x));
        m1 = fmaxf(m1, fmaxf(a.y, b.y));
        m2 = fmaxf(m2, fmaxf(a.z, b.z));
        m3 = fmaxf(m3, fmaxf(a.w, b.w));
    }
    if (j < end) {
        int s0 = g_srcs[j];
        float4 a = *(const float4*)&g_u2[s0 * 128 + lane * 4];
        m0 = fmaxf(m0, a.x); m1 = fmaxf(m1, a.y);
        m2 = fmaxf(m2, a.z); m3 = fmaxf(m3, a.w);
    }
    float4 v = *(const float4*)&g_v2[node * 128 + lane * 4];
    float h0 = fmaxf(m0 - v.x, 0.0f);
    float h1 = fmaxf(m1 - v.y, 0.0f);
    float h2 = fmaxf(m2 - v.z, 0.0f);
    float h3 = fmaxf(m3 - v.w, 0.0f);

    int c = lane * 4;
    const float* w0 = Wc + (c + 0) * 5;
    const float* w1 = Wc + (c + 1) * 5;
    const float* w2 = Wc + (c + 2) * 5;
    const float* w3 = Wc + (c + 3) * 5;
    float a0 = h0 * w0[0] + h1 * w1[0] + h2 * w2[0] + h3 * w3[0];
    float a1 = h0 * w0[1] + h1 * w1[1] + h2 * w2[1] + h3 * w3[1];
    float a2 = h0 * w0[2] + h1 * w1[2] + h2 * w2[2] + h3 * w3[2];
    float a3 = h0 * w0[3] + h1 * w1[3] + h2 * w2[3] + h3 * w3[3];
    float a4 = h0 * w0[4] + h1 * w1[4] + h2 * w2[4] + h3 * w3[4];
#pragma unroll
    for (int o = 16; o; o >>= 1) {
        a0 += __shfl_xor_sync(0xFFFFFFFFu, a0, o);
        a1 += __shfl_xor_sync(0xFFFFFFFFu, a1, o);
        a2 += __shfl_xor_sync(0xFFFFFFFFu, a2, o);
        a3 += __shfl_xor_sync(0xFFFFFFFFu, a3, o);
        a4 += __shfl_xor_sync(0xFFFFFFFFu, a4, o);
    }
    if (lane == 0) {
        float l0 = a0 + bc[0], l1 = a1 + bc[1], l2 = a2 + bc[2];
        float l3 = a3 + bc[3], l4 = a4 + bc[4];
        float mm = fmaxf(fmaxf(fmaxf(l0, l1), fmaxf(l2, l3)), l4);
        float s = expf(l0 - mm) + expf(l1 - mm) + expf(l2 - mm) +
                  expf(l3 - mm) + expf(l4 - mm);
        float lse = mm + logf(s);
        float* o = out + node * 5;
        o[0] = l0 - lse; o[1] = l1 - lse; o[2] = l2 - lse;
        o[3] = l3 - lse; o[4] = l4 - lse;
    }
}

// ---------------- launch ------------------------------------------------------
extern "C" void kernel_launch(void* const* d_in, const int* in_sizes, int n_in,
                              void* d_out, int out_size) {
    const float* x  = (const float*)d_in[0];
    const int*   ei = (const int*)d_in[1];
    const float* W1 = (const float*)d_in[2];
    const float* b1 = (const float*)d_in[3];
    const float* W2 = (const float*)d_in[4];
    const float* b2 = (const float*)d_in[5];
    const float* Wc = (const float*)d_in[6];
    const float* bc = (const float*)d_in[7];
    float* out = (float*)d_out;

    int n = in_sizes[0] / 3;   // 100000
    int e = in_sizes[1] / 2;   // 1600000
    const int* src = ei;
    const int* dst = ei + e;

    const int T = 256;
    int nb = (n + 1023) / 1024;

    k_u1v1     <<<(n * 64 + T - 1) / T, T>>>(x, W1, b1, n);
    k_hist     <<<(e + T - 1) / T, T>>>(dst, e);
    k_scan_block<<<nb, 1024>>>(n);
    k_scan_part <<<1, 1024>>>(nb);
    k_scan_add  <<<(n + T - 1) / T, T>>>(n);
    k_scatter   <<<(e + T - 1) / T, T>>>(src, dst, e);
    k_agg1      <<<(n * 32 + T - 1) / T, T>>>(n);
    k_u2v2      <<<n, 128>>>(x, W2, b2, n);
    k_agg2out   <<<(n * 32 + T - 1) / T, T>>>(Wc, bc, out, n);
}

// round 3
// speedup vs baseline: 5.4468x; 1.9860x over previous
#include <cuda_runtime.h>
#include <math_constants.h>

// ---------------- scratch (device globals; no allocation allowed) ----------
#define NMAX 131072
#define EMAX 2097152

__device__ float g_u1[NMAX * 64];
__device__ float g_v1[NMAX * 64];
__device__ float g_h1[NMAX * 64];
__device__ float g_u2[NMAX * 128];
__device__ float g_v2[NMAX * 128];
__device__ int   g_cnt[NMAX];      // zero-initialized at load; re-zeroed in k_scan_add
__device__ int   g_off[NMAX + 1];
__device__ int   g_cur[NMAX];
__device__ int   g_part[1024];
__device__ int   g_srcs[EMAX];

// ---------------- prep: u1/v1 per node + dst histogram (merged) -------------
// u1 = x@(W1a+W1b)+b1, v1 = x@W1b   (W1: [6,64] row-major)
__global__ void k_prep(const float* __restrict__ x, const float* __restrict__ W1,
                       const float* __restrict__ b1, const int* __restrict__ dst,
                       int n, int e) {
    int i = blockIdx.x * blockDim.x + threadIdx.x;
    int t1 = n * 64;
    if (i < t1) {
        int node = i >> 6, c = i & 63;
        float x0 = x[node * 3 + 0], x1 = x[node * 3 + 1], x2 = x[node * 3 + 2];
        float wa0 = W1[0 * 64 + c], wa1 = W1[1 * 64 + c], wa2 = W1[2 * 64 + c];
        float wb0 = W1[3 * 64 + c], wb1 = W1[4 * 64 + c], wb2 = W1[5 * 64 + c];
        float v = x0 * wb0 + x1 * wb1 + x2 * wb2;
        float u = x0 * (wa0 + wb0) + x1 * (wa1 + wb1) + x2 * (wa2 + wb2) + b1[c];
        g_u1[i] = u;
        g_v1[i] = v;
    } else {
        int j = i - t1;
        if (j < e) atomicAdd(&g_cnt[dst[j]], 1);
    }
}

// ---------------- CSR build (dst-sorted) ------------------------------------

__global__ void k_scan_block(int n) {
    __shared__ int sh[1024];
    int i = blockIdx.x * 1024 + threadIdx.x;
    int v = (i < n) ? g_cnt[i] : 0;
    sh[threadIdx.x] = v;
    __syncthreads();
#pragma unroll
    for (int o = 1; o < 1024; o <<= 1) {
        int t = (threadIdx.x >= o) ? sh[threadIdx.x - o] : 0;
        __syncthreads();
        sh[threadIdx.x] += t;
        __syncthreads();
    }
    if (i < n) g_off[i] = sh[threadIdx.x] - v;  // block-local exclusive
    if (threadIdx.x == 1023) g_part[blockIdx.x] = sh[1023];
}

__global__ void k_scan_part(int nb) {
    __shared__ int sh[1024];
    int v = (threadIdx.x < nb) ? g_part[threadIdx.x] : 0;
    sh[threadIdx.x] = v;
    __syncthreads();
#pragma unroll
    for (int o = 1; o < 1024; o <<= 1) {
        int t = (threadIdx.x >= o) ? sh[threadIdx.x - o] : 0;
        __syncthreads();
        sh[threadIdx.x] += t;
        __syncthreads();
    }
    if (threadIdx.x < nb) g_part[threadIdx.x] = sh[threadIdx.x] - v;  // exclusive
}

// finalize offsets + reset g_cnt to 0 for the next replay (read-then-zero)
__global__ void k_scan_add(int n) {
    int i = blockIdx.x * blockDim.x + threadIdx.x;
    if (i >= n) return;
    int o = g_off[i] + g_part[i >> 10];
    int c = g_cnt[i];
    g_cnt[i] = 0;
    g_off[i] = o;
    g_cur[i] = o;
    if (i == n - 1) g_off[n] = o + c;
}

__global__ void k_scatter(const int* __restrict__ src, const int* __restrict__ dst,
                          int e) {
    int i = blockIdx.x * blockDim.x + threadIdx.x;
    if (i >= e) return;
    int d = dst[i];
    int p = atomicAdd(&g_cur[d], 1);
    g_srcs[p] = src[i];
}

// ---------------- aggregation ------------------------------------------------

// layer-1 gather-max + relu: one warp per node, 2 comps per lane, 4-edge unroll
__global__ void k_agg1(int n) {
    int gt = blockIdx.x * blockDim.x + threadIdx.x;
    int node = gt >> 5, lane = gt & 31;
    if (node >= n) return;
    int off = g_off[node], end = g_off[node + 1];
    float mx = -CUDART_INF_F, my = -CUDART_INF_F;
    int j = off;
    for (; j + 3 < end; j += 4) {
        int s0 = g_srcs[j], s1 = g_srcs[j + 1], s2 = g_srcs[j + 2], s3 = g_srcs[j + 3];
        float2 a = *(const float2*)&g_u1[s0 * 64 + lane * 2];
        float2 b = *(const float2*)&g_u1[s1 * 64 + lane * 2];
        float2 c = *(const float2*)&g_u1[s2 * 64 + lane * 2];
        float2 d = *(const float2*)&g_u1[s3 * 64 + lane * 2];
        mx = fmaxf(mx, fmaxf(fmaxf(a.x, b.x), fmaxf(c.x, d.x)));
        my = fmaxf(my, fmaxf(fmaxf(a.y, b.y), fmaxf(c.y, d.y)));
    }
    for (; j < end; j++) {
        int s0 = g_srcs[j];
        float2 a = *(const float2*)&g_u1[s0 * 64 + lane * 2];
        mx = fmaxf(mx, a.x);
        my = fmaxf(my, a.y);
    }
    float2 v = *(const float2*)&g_v1[node * 64 + lane * 2];
    float2 h;
    h.x = fmaxf(mx - v.x, 0.0f);
    h.y = fmaxf(my - v.y, 0.0f);
    *(float2*)&g_h1[node * 64 + lane * 2] = h;
}

// layer 2 per-node, register-tiled GEMM:
// U2[n,128] = H1[n,64] @ W2[0:64] + b2 + V2 ;  V2[n,128] = x[n,:3] @ W2[64:67]
// Block: 32 nodes x 128 cols. 256 threads, each computes 4 nodes x 4 cols.
__global__ void k_u2v2(const float* __restrict__ x, const float* __restrict__ W2,
                       const float* __restrict__ b2, int n) {
    __shared__ float sW[64][128];
    __shared__ float sWx[3][128];
    __shared__ float sH[32][64];
    __shared__ float sx[32][3];
    int node0 = blockIdx.x * 32;
    int t = threadIdx.x;

    // stage W2 rows 0..63 (8192 floats)
    for (int i = t * 4; i < 64 * 128; i += 256 * 4)
        *(float4*)&sW[0][i] = *(const float4*)&W2[i];
    // stage W2 rows 64..66 (384 floats)
    if (t < 96) {
        int i = t * 4;
        *(float4*)&sWx[i >> 7][i & 127] = *(const float4*)&W2[64 * 128 + i];
    }
    // stage H tile (32x64)
    for (int i = t * 4; i < 32 * 64; i += 256 * 4) {
        int r = i >> 6, c = i & 63;
        int node = node0 + r;
        float4 hv = make_float4(0.f, 0.f, 0.f, 0.f);
        if (node < n) hv = *(const float4*)&g_h1[node * 64 + c];
        *(float4*)&sH[r][c] = hv;
    }
    // stage x tile (32x3)
    if (t < 96) {
        int r = t / 3, c = t % 3;
        int node = node0 + r;
        sx[r][c] = (node < n) ? x[node * 3 + c] : 0.f;
    }
    __syncthreads();

    int cg = (t & 31) << 2;   // col base 0..124
    int ng = (t >> 5) << 2;   // node base 0..28
    float4 acc[4];
#pragma unroll
    for (int i = 0; i < 4; i++) acc[i] = make_float4(0.f, 0.f, 0.f, 0.f);

#pragma unroll
    for (int k = 0; k < 64; k++) {
        float4 w = *(float4*)&sW[k][cg];
        float h0 = sH[ng + 0][k], h1 = sH[ng + 1][k];
        float h2 = sH[ng + 2][k], h3 = sH[ng + 3][k];
        acc[0].x += h0 * w.x; acc[0].y += h0 * w.y; acc[0].z += h0 * w.z; acc[0].w += h0 * w.w;
        acc[1].x += h1 * w.x; acc[1].y += h1 * w.y; acc[1].z += h1 * w.z; acc[1].w += h1 * w.w;
        acc[2].x += h2 * w.x; acc[2].y += h2 * w.y; acc[2].z += h2 * w.z; acc[2].w += h2 * w.w;
        acc[3].x += h3 * w.x; acc[3].y += h3 * w.y; acc[3].z += h3 * w.z; acc[3].w += h3 * w.w;
    }

    float4 bb  = *(const float4*)&b2[cg];
    float4 wx0 = *(float4*)&sWx[0][cg];
    float4 wx1 = *(float4*)&sWx[1][cg];
    float4 wx2 = *(float4*)&sWx[2][cg];

#pragma unroll
    for (int i = 0; i < 4; i++) {
        int node = node0 + ng + i;
        if (node >= n) continue;
        float x0 = sx[ng + i][0], x1 = sx[ng + i][1], x2 = sx[ng + i][2];
        float4 vv;
        vv.x = x0 * wx0.x + x1 * wx1.x + x2 * wx2.x;
        vv.y = x0 * wx0.y + x1 * wx1.y + x2 * wx2.y;
        vv.z = x0 * wx0.z + x1 * wx1.z + x2 * wx2.z;
        vv.w = x0 * wx0.w + x1 * wx1.w + x2 * wx2.w;
        float4 uu;
        uu.x = acc[i].x + bb.x + vv.x;
        uu.y = acc[i].y + bb.y + vv.y;
        uu.z = acc[i].z + bb.z + vv.z;
        uu.w = acc[i].w + bb.w + vv.w;
        *(float4*)&g_u2[node * 128 + cg] = uu;
        *(float4*)&g_v2[node * 128 + cg] = vv;
    }
}

// layer-2 gather-max fused with output head: one warp per node, 4 comps/lane
__global__ void k_agg2out(const float* __restrict__ Wc, const float* __restrict__ bc,
                          float* __restrict__ out, int n) {
    int gt = blockIdx.x * blockDim.x + threadIdx.x;
    int node = gt >> 5, lane = gt & 31;
    if (node >= n) return;
    int off = g_off[node], end = g_off[node + 1];
    float m0 = -CUDART_INF_F, m1 = m0, m2 = m0, m3 = m0;
    int j = off;
    for (; j + 3 < end; j += 4) {
        int s0 = g_srcs[j], s1 = g_srcs[j + 1], s2 = g_srcs[j + 2], s3 = g_srcs[j + 3];
        float4 a = *(const float4*)&g_u2[s0 * 128 + lane * 4];
        float4 b = *(const float4*)&g_u2[s1 * 128 + lane * 4];
        float4 c = *(const float4*)&g_u2[s2 * 128 + lane * 4];
        float4 d = *(const float4*)&g_u2[s3 * 128 + lane * 4];
        m0 = fmaxf(m0, fmaxf(fmaxf(a.x, b.x), fmaxf(c.x, d.x)));
        m1 = fmaxf(m1, fmaxf(fmaxf(a.y, b.y), fmaxf(c.y, d.y)));
        m2 = fmaxf(m2, fmaxf(fmaxf(a.z, b.z), fmaxf(c.z, d.z)));
        m3 = fmaxf(m3, fmaxf(fmaxf(a.w, b.w), fmaxf(c.w, d.w)));
    }
    for (; j < end; j++) {
        int s0 = g_srcs[j];
        float4 a = *(const float4*)&g_u2[s0 * 128 + lane * 4];
        m0 = fmaxf(m0, a.x); m1 = fmaxf(m1, a.y);
        m2 = fmaxf(m2, a.z); m3 = fmaxf(m3, a.w);
    }
    float4 v = *(const float4*)&g_v2[node * 128 + lane * 4];
    float h0 = fmaxf(m0 - v.x, 0.0f);
    float h1 = fmaxf(m1 - v.y, 0.0f);
    float h2 = fmaxf(m2 - v.z, 0.0f);
    float h3 = fmaxf(m3 - v.w, 0.0f);

    int c = lane * 4;
    const float* w0 = Wc + (c + 0) * 5;
    const float* w1 = Wc + (c + 1) * 5;
    const float* w2 = Wc + (c + 2) * 5;
    const float* w3 = Wc + (c + 3) * 5;
    float a0 = h0 * w0[0] + h1 * w1[0] + h2 * w2[0] + h3 * w3[0];
    float a1 = h0 * w0[1] + h1 * w1[1] + h2 * w2[1] + h3 * w3[1];
    float a2 = h0 * w0[2] + h1 * w1[2] + h2 * w2[2] + h3 * w3[2];
    float a3 = h0 * w0[3] + h1 * w1[3] + h2 * w2[3] + h3 * w3[3];
    float a4 = h0 * w0[4] + h1 * w1[4] + h2 * w2[4] + h3 * w3[4];
#pragma unroll
    for (int o = 16; o; o >>= 1) {
        a0 += __shfl_xor_sync(0xFFFFFFFFu, a0, o);
        a1 += __shfl_xor_sync(0xFFFFFFFFu, a1, o);
        a2 += __shfl_xor_sync(0xFFFFFFFFu, a2, o);
        a3 += __shfl_xor_sync(0xFFFFFFFFu, a3, o);
        a4 += __shfl_xor_sync(0xFFFFFFFFu, a4, o);
    }
    if (lane == 0) {
        float l0 = a0 + bc[0], l1 = a1 + bc[1], l2 = a2 + bc[2];
        float l3 = a3 + bc[3], l4 = a4 + bc[4];
        float mm = fmaxf(fmaxf(fmaxf(l0, l1), fmaxf(l2, l3)), l4);
        float s = expf(l0 - mm) + expf(l1 - mm) + expf(l2 - mm) +
                  expf(l3 - mm) + expf(l4 - mm);
        float lse = mm + logf(s);
        float* o = out + node * 5;
        o[0] = l0 - lse; o[1] = l1 - lse; o[2] = l2 - lse;
        o[3] = l3 - lse; o[4] = l4 - lse;
    }
}

// ---------------- launch ------------------------------------------------------
extern "C" void kernel_launch(void* const* d_in, const int* in_sizes, int n_in,
                              void* d_out, int out_size) {
    const float* x  = (const float*)d_in[0];
    const int*   ei = (const int*)d_in[1];
    const float* W1 = (const float*)d_in[2];
    const float* b1 = (const float*)d_in[3];
    const float* W2 = (const float*)d_in[4];
    const float* b2 = (const float*)d_in[5];
    const float* Wc = (const float*)d_in[6];
    const float* bc = (const float*)d_in[7];
    float* out = (float*)d_out;

    int n = in_sizes[0] / 3;   // 100000
    int e = in_sizes[1] / 2;   // 1600000
    const int* src = ei;
    const int* dst = ei + e;

    const int T = 256;
    int nb = (n + 1023) / 1024;

    k_prep      <<<(n * 64 + e + T - 1) / T, T>>>(x, W1, b1, dst, n, e);
    k_scan_block<<<nb, 1024>>>(n);
    k_scan_part <<<1, 1024>>>(nb);
    k_scan_add  <<<(n + T - 1) / T, T>>>(n);
    k_scatter   <<<(e + T - 1) / T, T>>>(src, dst, e);
    k_agg1      <<<(n * 32 + T - 1) / T, T>>>(n);
    k_u2v2      <<<(n + 31) / 32, 256>>>(x, W2, b2, n);
    k_agg2out   <<<(n * 32 + T - 1) / T, T>>>(Wc, bc, out, n);
}

// round 4
// speedup vs baseline: 6.2867x; 1.1542x over previous
#include <cuda_runtime.h>
#include <cuda_fp16.h>
#include <math_constants.h>

// ---------------- scratch (device globals; no allocation allowed) ----------
#define NMAX 131072
#define EMAX 2097152

__device__ __half2 g_u1h[NMAX * 32];   // u1 in fp16, 32 half2 per node
__device__ float   g_v1[NMAX * 64];
__device__ float   g_h1[NMAX * 64];
__device__ __half2 g_u2h[NMAX * 64];   // u2 in fp16, 64 half2 per node
__device__ float   g_v2[NMAX * 128];
__device__ int     g_cnt[NMAX];        // zero at load; re-zeroed in k_alloc
__device__ int     g_off[NMAX];
__device__ int     g_end[NMAX];
__device__ int     g_cur[NMAX];
__device__ int     g_cursor;           // zero at load; reset in k_prep
__device__ int     g_srcs[EMAX];

// ---------------- prep: u1/v1 per node (fp16 u1) + dst histogram ------------
// u1 = x@(W1a+W1b)+b1, v1 = x@W1b   (W1: [6,64] row-major)
// one thread per (node, component-pair)
__global__ void k_prep(const float* __restrict__ x, const float* __restrict__ W1,
                       const float* __restrict__ b1, const int* __restrict__ dst,
                       int n, int e) {
    int i = blockIdx.x * blockDim.x + threadIdx.x;
    if (i == 0) g_cursor = 0;
    int t1 = n * 32;
    if (i < t1) {
        int node = i >> 5, p = i & 31;
        int c0 = p * 2, c1 = p * 2 + 1;
        float x0 = x[node * 3 + 0], x1 = x[node * 3 + 1], x2 = x[node * 3 + 2];
        float u[2], v[2];
#pragma unroll
        for (int k = 0; k < 2; k++) {
            int c = (k == 0) ? c0 : c1;
            float wa0 = W1[0 * 64 + c], wa1 = W1[1 * 64 + c], wa2 = W1[2 * 64 + c];
            float wb0 = W1[3 * 64 + c], wb1 = W1[4 * 64 + c], wb2 = W1[5 * 64 + c];
            v[k] = x0 * wb0 + x1 * wb1 + x2 * wb2;
            u[k] = x0 * (wa0 + wb0) + x1 * (wa1 + wb1) + x2 * (wa2 + wb2) + b1[c];
        }
        g_u1h[i] = __floats2half2_rn(u[0], u[1]);
        *(float2*)&g_v1[node * 64 + c0] = make_float2(v[0], v[1]);
    } else {
        int j = i - t1;
        if (j < e) atomicAdd(&g_cnt[dst[j]], 1);
    }
}

// ---------------- CSR ranges via atomic cursor (order-free, set-deterministic)
__global__ void k_alloc(int n) {
    int i = blockIdx.x * blockDim.x + threadIdx.x;
    if (i >= n) return;
    int c = g_cnt[i];
    g_cnt[i] = 0;
    int o = atomicAdd(&g_cursor, c);
    g_off[i] = o;
    g_end[i] = o + c;
    g_cur[i] = o;
}

__global__ void k_scatter(const int* __restrict__ src, const int* __restrict__ dst,
                          int e) {
    int i = blockIdx.x * blockDim.x + threadIdx.x;
    if (i >= e) return;
    int d = dst[i];
    int p = atomicAdd(&g_cur[d], 1);
    g_srcs[p] = src[i];
}

// ---------------- aggregation ------------------------------------------------

// layer-1 gather-max + relu: one warp/node, 1 half2 per lane, 4-edge unroll
__global__ void k_agg1(int n) {
    int gt = blockIdx.x * blockDim.x + threadIdx.x;
    int node = gt >> 5, lane = gt & 31;
    if (node >= n) return;
    int off = g_off[node], end = g_end[node];
    __half2 m = __halves2half2(__ushort_as_half(0xFC00), __ushort_as_half(0xFC00));
    int j = off;
    for (; j + 3 < end; j += 4) {
        int s0 = g_srcs[j], s1 = g_srcs[j + 1], s2 = g_srcs[j + 2], s3 = g_srcs[j + 3];
        __half2 a = g_u1h[s0 * 32 + lane];
        __half2 b = g_u1h[s1 * 32 + lane];
        __half2 c = g_u1h[s2 * 32 + lane];
        __half2 d = g_u1h[s3 * 32 + lane];
        m = __hmax2(m, __hmax2(__hmax2(a, b), __hmax2(c, d)));
    }
    for (; j < end; j++)
        m = __hmax2(m, g_u1h[g_srcs[j] * 32 + lane]);
    float2 mf = __half22float2(m);
    float2 v = *(const float2*)&g_v1[node * 64 + lane * 2];
    float2 h;
    h.x = fmaxf(mf.x - v.x, 0.0f);
    h.y = fmaxf(mf.y - v.y, 0.0f);
    *(float2*)&g_h1[node * 64 + lane * 2] = h;
}

// layer 2 per-node, register-tiled GEMM:
// U2[n,128] = H1[n,64] @ W2[0:64] + b2 + V2 ;  V2[n,128] = x[n,:3] @ W2[64:67]
// Block: 32 nodes x 128 cols. 256 threads, 4 nodes x 4 cols each.
__global__ void k_u2v2(const float* __restrict__ x, const float* __restrict__ W2,
                       const float* __restrict__ b2, int n) {
    __shared__ float sW[64][128];
    __shared__ float sWx[3][128];
    __shared__ float sH[32][64];
    __shared__ float sx[32][3];
    int node0 = blockIdx.x * 32;
    int t = threadIdx.x;

    for (int i = t * 4; i < 64 * 128; i += 256 * 4)
        *(float4*)&sW[0][i] = *(const float4*)&W2[i];
    if (t < 96) {
        int i = t * 4;
        *(float4*)&sWx[i >> 7][i & 127] = *(const float4*)&W2[64 * 128 + i];
    }
    for (int i = t * 4; i < 32 * 64; i += 256 * 4) {
        int r = i >> 6, c = i & 63;
        int node = node0 + r;
        float4 hv = make_float4(0.f, 0.f, 0.f, 0.f);
        if (node < n) hv = *(const float4*)&g_h1[node * 64 + c];
        *(float4*)&sH[r][c] = hv;
    }
    if (t < 96) {
        int r = t / 3, c = t % 3;
        int node = node0 + r;
        sx[r][c] = (node < n) ? x[node * 3 + c] : 0.f;
    }
    __syncthreads();

    int cg = (t & 31) << 2;
    int ng = (t >> 5) << 2;
    float4 acc[4];
#pragma unroll
    for (int i = 0; i < 4; i++) acc[i] = make_float4(0.f, 0.f, 0.f, 0.f);

#pragma unroll
    for (int k = 0; k < 64; k++) {
        float4 w = *(float4*)&sW[k][cg];
        float h0 = sH[ng + 0][k], h1 = sH[ng + 1][k];
        float h2 = sH[ng + 2][k], h3 = sH[ng + 3][k];
        acc[0].x += h0 * w.x; acc[0].y += h0 * w.y; acc[0].z += h0 * w.z; acc[0].w += h0 * w.w;
        acc[1].x += h1 * w.x; acc[1].y += h1 * w.y; acc[1].z += h1 * w.z; acc[1].w += h1 * w.w;
        acc[2].x += h2 * w.x; acc[2].y += h2 * w.y; acc[2].z += h2 * w.z; acc[2].w += h2 * w.w;
        acc[3].x += h3 * w.x; acc[3].y += h3 * w.y; acc[3].z += h3 * w.z; acc[3].w += h3 * w.w;
    }

    float4 bb  = *(const float4*)&b2[cg];
    float4 wx0 = *(float4*)&sWx[0][cg];
    float4 wx1 = *(float4*)&sWx[1][cg];
    float4 wx2 = *(float4*)&sWx[2][cg];

#pragma unroll
    for (int i = 0; i < 4; i++) {
        int node = node0 + ng + i;
        if (node >= n) continue;
        float x0 = sx[ng + i][0], x1 = sx[ng + i][1], x2 = sx[ng + i][2];
        float4 vv;
        vv.x = x0 * wx0.x + x1 * wx1.x + x2 * wx2.x;
        vv.y = x0 * wx0.y + x1 * wx1.y + x2 * wx2.y;
        vv.z = x0 * wx0.z + x1 * wx1.z + x2 * wx2.z;
        vv.w = x0 * wx0.w + x1 * wx1.w + x2 * wx2.w;
        float4 uu;
        uu.x = acc[i].x + bb.x + vv.x;
        uu.y = acc[i].y + bb.y + vv.y;
        uu.z = acc[i].z + bb.z + vv.z;
        uu.w = acc[i].w + bb.w + vv.w;
        g_u2h[node * 64 + (cg >> 1) + 0] = __floats2half2_rn(uu.x, uu.y);
        g_u2h[node * 64 + (cg >> 1) + 1] = __floats2half2_rn(uu.z, uu.w);
        *(float4*)&g_v2[node * 128 + cg] = vv;
    }
}

// layer-2 gather-max fused with output head: one warp/node, 2 half2 per lane
__global__ void k_agg2out(const float* __restrict__ Wc, const float* __restrict__ bc,
                          float* __restrict__ out, int n) {
    int gt = blockIdx.x * blockDim.x + threadIdx.x;
    int node = gt >> 5, lane = gt & 31;
    if (node >= n) return;
    int off = g_off[node], end = g_end[node];
    __half2 m0 = __halves2half2(__ushort_as_half(0xFC00), __ushort_as_half(0xFC00));
    __half2 m1 = m0;
    int j = off;
    for (; j + 3 < end; j += 4) {
        int s0 = g_srcs[j], s1 = g_srcs[j + 1], s2 = g_srcs[j + 2], s3 = g_srcs[j + 3];
        uint2 ra = *(const uint2*)&g_u2h[s0 * 64 + lane * 2];
        uint2 rb = *(const uint2*)&g_u2h[s1 * 64 + lane * 2];
        uint2 rc = *(const uint2*)&g_u2h[s2 * 64 + lane * 2];
        uint2 rd = *(const uint2*)&g_u2h[s3 * 64 + lane * 2];
        m0 = __hmax2(m0, __hmax2(__hmax2(*(__half2*)&ra.x, *(__half2*)&rb.x),
                                 __hmax2(*(__half2*)&rc.x, *(__half2*)&rd.x)));
        m1 = __hmax2(m1, __hmax2(__hmax2(*(__half2*)&ra.y, *(__half2*)&rb.y),
                                 __hmax2(*(__half2*)&rc.y, *(__half2*)&rd.y)));
    }
    for (; j < end; j++) {
        uint2 ra = *(const uint2*)&g_u2h[g_srcs[j] * 64 + lane * 2];
        m0 = __hmax2(m0, *(__half2*)&ra.x);
        m1 = __hmax2(m1, *(__half2*)&ra.y);
    }
    float2 f0 = __half22float2(m0);
    float2 f1 = __half22float2(m1);
    float4 v = *(const float4*)&g_v2[node * 128 + lane * 4];
    float h0 = fmaxf(f0.x - v.x, 0.0f);
    float h1 = fmaxf(f0.y - v.y, 0.0f);
    float h2 = fmaxf(f1.x - v.z, 0.0f);
    float h3 = fmaxf(f1.y - v.w, 0.0f);

    int c = lane * 4;
    const float* w0 = Wc + (c + 0) * 5;
    const float* w1 = Wc + (c + 1) * 5;
    const float* w2 = Wc + (c + 2) * 5;
    const float* w3 = Wc + (c + 3) * 5;
    float a0 = h0 * w0[0] + h1 * w1[0] + h2 * w2[0] + h3 * w3[0];
    float a1 = h0 * w0[1] + h1 * w1[1] + h2 * w2[1] + h3 * w3[1];
    float a2 = h0 * w0[2] + h1 * w1[2] + h2 * w2[2] + h3 * w3[2];
    float a3 = h0 * w0[3] + h1 * w1[3] + h2 * w2[3] + h3 * w3[3];
    float a4 = h0 * w0[4] + h1 * w1[4] + h2 * w2[4] + h3 * w3[4];
#pragma unroll
    for (int o = 16; o; o >>= 1) {
        a0 += __shfl_xor_sync(0xFFFFFFFFu, a0, o);
        a1 += __shfl_xor_sync(0xFFFFFFFFu, a1, o);
        a2 += __shfl_xor_sync(0xFFFFFFFFu, a2, o);
        a3 += __shfl_xor_sync(0xFFFFFFFFu, a3, o);
        a4 += __shfl_xor_sync(0xFFFFFFFFu, a4, o);
    }
    if (lane == 0) {
        float l0 = a0 + bc[0], l1 = a1 + bc[1], l2 = a2 + bc[2];
        float l3 = a3 + bc[3], l4 = a4 + bc[4];
        float mm = fmaxf(fmaxf(fmaxf(l0, l1), fmaxf(l2, l3)), l4);
        float s = expf(l0 - mm) + expf(l1 - mm) + expf(l2 - mm) +
                  expf(l3 - mm) + expf(l4 - mm);
        float lse = mm + logf(s);
        float* o = out + node * 5;
        o[0] = l0 - lse; o[1] = l1 - lse; o[2] = l2 - lse;
        o[3] = l3 - lse; o[4] = l4 - lse;
    }
}

// ---------------- launch ------------------------------------------------------
extern "C" void kernel_launch(void* const* d_in, const int* in_sizes, int n_in,
                              void* d_out, int out_size) {
    const float* x  = (const float*)d_in[0];
    const int*   ei = (const int*)d_in[1];
    const float* W1 = (const float*)d_in[2];
    const float* b1 = (const float*)d_in[3];
    const float* W2 = (const float*)d_in[4];
    const float* b2 = (const float*)d_in[5];
    const float* Wc = (const float*)d_in[6];
    const float* bc = (const float*)d_in[7];
    float* out = (float*)d_out;

    int n = in_sizes[0] / 3;   // 100000
    int e = in_sizes[1] / 2;   // 1600000
    const int* src = ei;
    const int* dst = ei + e;

    const int T = 256;

    k_prep    <<<(n * 32 + e + T - 1) / T, T>>>(x, W1, b1, dst, n, e);
    k_alloc   <<<(n + T - 1) / T, T>>>(n);
    k_scatter <<<(e + T - 1) / T, T>>>(src, dst, e);
    k_agg1    <<<(n * 32 + T - 1) / T, T>>>(n);
    k_u2v2    <<<(n + 31) / 32, 256>>>(x, W2, b2, n);
    k_agg2out <<<(n * 32 + T - 1) / T, T>>>(Wc, bc, out, n);
}

// round 5
// speedup vs baseline: 6.3537x; 1.0107x over previous
#include <cuda_runtime.h>
#include <cuda_fp16.h>
#include <mma.h>
#include <math_constants.h>

using namespace nvcuda;

// ---------------- scratch (device globals; no allocation allowed) ----------
#define NMAX 131072
#define EMAX 2097152   // >= E + 3*N padding

__device__ __align__(16) __half2 g_u1h[NMAX * 32];   // u1 fp16, 32 half2/node
__device__ __align__(16) float   g_v1[NMAX * 64];
__device__ __align__(16) __half  g_h1h[NMAX * 64];   // h1 fp16
__device__ __align__(16) __half2 g_u2h[NMAX * 64];   // u2 fp16, 64 half2/node
__device__ __align__(16) float   g_v2[NMAX * 128];
__device__ int g_cnt[NMAX];          // zero at load; re-zeroed in k_alloc
__device__ int g_off[NMAX];
__device__ int g_end[NMAX];          // padded end (off + ceil(cnt/4)*4)
__device__ int g_cur[NMAX];
__device__ int g_cursor;             // reset in k_prep
__device__ __align__(16) int g_srcs[EMAX];

// ---------------- prep: u1/v1 per node (fp16 u1) + dst histogram ------------
__global__ void k_prep(const float* __restrict__ x, const float* __restrict__ W1,
                       const float* __restrict__ b1, const int* __restrict__ dst,
                       int n, int e) {
    int i = blockIdx.x * blockDim.x + threadIdx.x;
    if (i == 0) g_cursor = 0;
    int t1 = n * 32;
    if (i < t1) {
        int node = i >> 5, p = i & 31;
        float x0 = x[node * 3 + 0], x1 = x[node * 3 + 1], x2 = x[node * 3 + 2];
        float u[2], v[2];
#pragma unroll
        for (int k = 0; k < 2; k++) {
            int c = p * 2 + k;
            float wa0 = W1[0 * 64 + c], wa1 = W1[1 * 64 + c], wa2 = W1[2 * 64 + c];
            float wb0 = W1[3 * 64 + c], wb1 = W1[4 * 64 + c], wb2 = W1[5 * 64 + c];
            v[k] = x0 * wb0 + x1 * wb1 + x2 * wb2;
            u[k] = x0 * (wa0 + wb0) + x1 * (wa1 + wb1) + x2 * (wa2 + wb2) + b1[c];
        }
        g_u1h[i] = __floats2half2_rn(u[0], u[1]);
        *(float2*)&g_v1[node * 64 + p * 2] = make_float2(v[0], v[1]);
    } else {
        int j = i - t1;
        if (j < e) atomicAdd(&g_cnt[dst[j]], 1);
    }
}

// ---------------- CSR ranges via atomic cursor, padded to multiple of 4 -----
__global__ void k_alloc(int n) {
    int i = blockIdx.x * blockDim.x + threadIdx.x;
    if (i >= n) return;
    int c = g_cnt[i];
    g_cnt[i] = 0;
    int len = (c + 3) & ~3;
    int o = atomicAdd(&g_cursor, len);
    g_off[i] = o;
    g_end[i] = o + len;
    g_cur[i] = o;
}

__global__ void k_scatter(const int* __restrict__ src, const int* __restrict__ dst,
                          int e) {
    int i = blockIdx.x * blockDim.x + threadIdx.x;
    if (i >= e) return;
    int d = dst[i];
    int p = atomicAdd(&g_cur[d], 1);
    g_srcs[p] = src[i];
}

// fill pad slots with a duplicate of the node's first src (max-invariant)
__global__ void k_pad(int n) {
    int i = blockIdx.x * blockDim.x + threadIdx.x;
    if (i >= n) return;
    int cur = g_cur[i], end = g_end[i], off = g_off[i];
    if (cur == off) return;          // deg 0: end==off, nothing to pad
    int s = g_srcs[off];
    for (int p = cur; p < end; p++) g_srcs[p] = s;
}

// ---------------- aggregation ------------------------------------------------

// layer-1 gather-max + relu -> h1 (fp16). One warp/node, exact 4-edge unroll.
__global__ void k_agg1(int n) {
    int gt = blockIdx.x * blockDim.x + threadIdx.x;
    int node = gt >> 5, lane = gt & 31;
    if (node >= n) return;
    int off = g_off[node], end = g_end[node];
    __half2 m = __halves2half2(__ushort_as_half(0xFC00), __ushort_as_half(0xFC00));
    for (int j = off; j < end; j += 4) {
        int4 s = *(const int4*)&g_srcs[j];
        __half2 a = g_u1h[s.x * 32 + lane];
        __half2 b = g_u1h[s.y * 32 + lane];
        __half2 c = g_u1h[s.z * 32 + lane];
        __half2 d = g_u1h[s.w * 32 + lane];
        m = __hmax2(m, __hmax2(__hmax2(a, b), __hmax2(c, d)));
    }
    float2 mf = __half22float2(m);
    float2 v = *(const float2*)&g_v1[node * 64 + lane * 2];
    float h0 = fmaxf(mf.x - v.x, 0.0f);
    float h1 = fmaxf(mf.y - v.y, 0.0f);
    *(__half2*)&g_h1h[node * 64 + lane * 2] = __floats2half2_rn(h0, h1);
}

// layer 2: U2 = H1 @ W2[0:64] + b2 + V2 ; V2 = x @ W2[64:67]
// Tensor-core GEMM: block = 64 nodes x 128 cols, 8 warps (4M x 2N), wmma 16x16x16.
__global__ void __launch_bounds__(256) k_u2v2(
        const float* __restrict__ x, const float* __restrict__ W2,
        const float* __restrict__ b2, int n) {
    __shared__ __align__(16) unsigned char sraw[32768];   // W2h+H  /  Acc
    __shared__ float sWx[3][128];
    __shared__ float sx[64][3];
    __half* sW2h = (__half*)sraw;            // [64][128] halves, 16 KB
    __half* sH   = (__half*)(sraw + 16384);  // [64][64]  halves,  8 KB
    float*  sAcc = (float*)sraw;             // [64][128] floats, 32 KB (epilogue)

    int node0 = blockIdx.x * 64;
    int t = threadIdx.x;
    int wid = t >> 5;

    // stage W2 rows 0..63 as fp16
    for (int i = t * 4; i < 8192; i += 1024) {
        float4 w = *(const float4*)&W2[i];
        ((__half2*)sW2h)[i / 2]     = __floats2half2_rn(w.x, w.y);
        ((__half2*)sW2h)[i / 2 + 1] = __floats2half2_rn(w.z, w.w);
    }
    // stage W2 rows 64..66 (fp32)
    if (t < 96) {
        int i = t * 4;
        *(float4*)&sWx[i >> 7][i & 127] = *(const float4*)&W2[64 * 128 + i];
    }
    // stage H tile (64x64 halves = 512 uint4)
    for (int i = t; i < 512; i += 256) {
        int r = i >> 3, q = i & 7;
        int node = node0 + r;
        uint4 v = make_uint4(0u, 0u, 0u, 0u);
        if (node < n) v = *(const uint4*)&g_h1h[node * 64 + q * 8];
        *(uint4*)&sH[r * 64 + q * 8] = v;
    }
    // stage x tile (64x3)
    if (t < 192) {
        int r = t / 3, c = t % 3;
        int node = node0 + r;
        sx[r][c] = (node < n) ? x[node * 3 + c] : 0.f;
    }
    __syncthreads();

    int wm = wid & 3;    // 4 m-tiles of 16 rows
    int wn = wid >> 2;   // 2 n-halves of 64 cols
    wmma::fragment<wmma::accumulator, 16, 16, 16, float> acc[4];
#pragma unroll
    for (int i = 0; i < 4; i++) wmma::fill_fragment(acc[i], 0.0f);
#pragma unroll
    for (int k = 0; k < 4; k++) {
        wmma::fragment<wmma::matrix_a, 16, 16, 16, __half, wmma::row_major> a;
        wmma::load_matrix_sync(a, sH + (wm * 16) * 64 + k * 16, 64);
#pragma unroll
        for (int nt = 0; nt < 4; nt++) {
            wmma::fragment<wmma::matrix_b, 16, 16, 16, __half, wmma::row_major> b;
            wmma::load_matrix_sync(b, sW2h + (k * 16) * 128 + wn * 64 + nt * 16, 128);
            wmma::mma_sync(acc[nt], a, b, acc[nt]);
        }
    }
    __syncthreads();   // done with sW2h/sH; reuse as sAcc
#pragma unroll
    for (int nt = 0; nt < 4; nt++)
        wmma::store_matrix_sync(sAcc + (wm * 16) * 128 + wn * 64 + nt * 16,
                                acc[nt], 128, wmma::mem_row_major);
    __syncthreads();

    // epilogue: u2h = acc + b2 + v2 (fp16), v2 (fp32)
    for (int i = t * 4; i < 8192; i += 1024) {
        int r = i >> 7, c = i & 127;
        int node = node0 + r;
        if (node >= n) continue;
        float4 a4 = *(float4*)&sAcc[i];
        float x0 = sx[r][0], x1 = sx[r][1], x2 = sx[r][2];
        float4 vv;
        vv.x = x0 * sWx[0][c + 0] + x1 * sWx[1][c + 0] + x2 * sWx[2][c + 0];
        vv.y = x0 * sWx[0][c + 1] + x1 * sWx[1][c + 1] + x2 * sWx[2][c + 1];
        vv.z = x0 * sWx[0][c + 2] + x1 * sWx[1][c + 2] + x2 * sWx[2][c + 2];
        vv.w = x0 * sWx[0][c + 3] + x1 * sWx[1][c + 3] + x2 * sWx[2][c + 3];
        float4 bb = *(const float4*)&b2[c];
        __half2 u01 = __floats2half2_rn(a4.x + bb.x + vv.x, a4.y + bb.y + vv.y);
        __half2 u23 = __floats2half2_rn(a4.z + bb.z + vv.z, a4.w + bb.w + vv.w);
        uint2 upk;
        upk.x = *(unsigned*)&u01;
        upk.y = *(unsigned*)&u23;
        *(uint2*)&g_u2h[node * 64 + (c >> 1)] = upk;
        *(float4*)&g_v2[node * 128 + c] = vv;
    }
}

// layer-2 gather-max fused with output head: one warp/node, exact 4-edge unroll
__global__ void k_agg2out(const float* __restrict__ Wc, const float* __restrict__ bc,
                          float* __restrict__ out, int n) {
    int gt = blockIdx.x * blockDim.x + threadIdx.x;
    int node = gt >> 5, lane = gt & 31;
    if (node >= n) return;
    int off = g_off[node], end = g_end[node];
    __half2 m0 = __halves2half2(__ushort_as_half(0xFC00), __ushort_as_half(0xFC00));
    __half2 m1 = m0;
    for (int j = off; j < end; j += 4) {
        int4 s = *(const int4*)&g_srcs[j];
        uint2 ra = *(const uint2*)&g_u2h[s.x * 64 + lane * 2];
        uint2 rb = *(const uint2*)&g_u2h[s.y * 64 + lane * 2];
        uint2 rc = *(const uint2*)&g_u2h[s.z * 64 + lane * 2];
        uint2 rd = *(const uint2*)&g_u2h[s.w * 64 + lane * 2];
        m0 = __hmax2(m0, __hmax2(__hmax2(*(__half2*)&ra.x, *(__half2*)&rb.x),
                                 __hmax2(*(__half2*)&rc.x, *(__half2*)&rd.x)));
        m1 = __hmax2(m1, __hmax2(__hmax2(*(__half2*)&ra.y, *(__half2*)&rb.y),
                                 __hmax2(*(__half2*)&rc.y, *(__half2*)&rd.y)));
    }
    float2 f0 = __half22float2(m0);
    float2 f1 = __half22float2(m1);
    float4 v = *(const float4*)&g_v2[node * 128 + lane * 4];
    float h0 = fmaxf(f0.x - v.x, 0.0f);
    float h1 = fmaxf(f0.y - v.y, 0.0f);
    float h2 = fmaxf(f1.x - v.z, 0.0f);
    float h3 = fmaxf(f1.y - v.w, 0.0f);

    int c = lane * 4;
    const float* w0 = Wc + (c + 0) * 5;
    const float* w1 = Wc + (c + 1) * 5;
    const float* w2 = Wc + (c + 2) * 5;
    const float* w3 = Wc + (c + 3) * 5;
    float a0 = h0 * w0[0] + h1 * w1[0] + h2 * w2[0] + h3 * w3[0];
    float a1 = h0 * w0[1] + h1 * w1[1] + h2 * w2[1] + h3 * w3[1];
    float a2 = h0 * w0[2] + h1 * w1[2] + h2 * w2[2] + h3 * w3[2];
    float a3 = h0 * w0[3] + h1 * w1[3] + h2 * w2[3] + h3 * w3[3];
    float a4 = h0 * w0[4] + h1 * w1[4] + h2 * w2[4] + h3 * w3[4];
#pragma unroll
    for (int o = 16; o; o >>= 1) {
        a0 += __shfl_xor_sync(0xFFFFFFFFu, a0, o);
        a1 += __shfl_xor_sync(0xFFFFFFFFu, a1, o);
        a2 += __shfl_xor_sync(0xFFFFFFFFu, a2, o);
        a3 += __shfl_xor_sync(0xFFFFFFFFu, a3, o);
        a4 += __shfl_xor_sync(0xFFFFFFFFu, a4, o);
    }
    if (lane == 0) {
        float l0 = a0 + bc[0], l1 = a1 + bc[1], l2 = a2 + bc[2];
        float l3 = a3 + bc[3], l4 = a4 + bc[4];
        float mm = fmaxf(fmaxf(fmaxf(l0, l1), fmaxf(l2, l3)), l4);
        float s = expf(l0 - mm) + expf(l1 - mm) + expf(l2 - mm) +
                  expf(l3 - mm) + expf(l4 - mm);
        float lse = mm + logf(s);
        float* o = out + node * 5;
        o[0] = l0 - lse; o[1] = l1 - lse; o[2] = l2 - lse;
        o[3] = l3 - lse; o[4] = l4 - lse;
    }
}

// ---------------- launch ------------------------------------------------------
extern "C" void kernel_launch(void* const* d_in, const int* in_sizes, int n_in,
                              void* d_out, int out_size) {
    const float* x  = (const float*)d_in[0];
    const int*   ei = (const int*)d_in[1];
    const float* W1 = (const float*)d_in[2];
    const float* b1 = (const float*)d_in[3];
    const float* W2 = (const float*)d_in[4];
    const float* b2 = (const float*)d_in[5];
    const float* Wc = (const float*)d_in[6];
    const float* bc = (const float*)d_in[7];
    float* out = (float*)d_out;

    int n = in_sizes[0] / 3;   // 100000
    int e = in_sizes[1] / 2;   // 1600000
    const int* src = ei;
    const int* dst = ei + e;

    const int T = 256;

    k_prep    <<<(n * 32 + e + T - 1) / T, T>>>(x, W1, b1, dst, n, e);
    k_alloc   <<<(n + T - 1) / T, T>>>(n);
    k_scatter <<<(e + T - 1) / T, T>>>(src, dst, e);
    k_pad     <<<(n + T - 1) / T, T>>>(n);
    k_agg1    <<<(n * 32 + T - 1) / T, T>>>(n);
    k_u2v2    <<<(n + 63) / 64, 256>>>(x, W2, b2, n);
    k_agg2out <<<(n * 32 + T - 1) / T, T>>>(Wc, bc, out, n);
}